// round 1
// baseline (speedup 1.0000x reference)
#include <cuda_runtime.h>
#include <cstdint>
#include <cstddef>

#define T_SEQ 512
#define BATCH 128
#define DIN   1024
#define DOUT  1024
#define N4    4096          // 4 gates * DOUT, gate-interleaved: n = unit*4 + gate
#define GRID_LSTM 128

// ---------------- static device scratch (no allocations allowed) ----------------
__device__ __align__(256) float g_Z  [(size_t)T_SEQ * BATCH * N4];   // 1 GiB: x-part preactivations (+bias)
__device__ __align__(256) float g_Wx [(size_t)N4 * DIN];             // packed tf32-rounded x-weights
__device__ __align__(256) float g_Wh [(size_t)N4 * DOUT];            // packed tf32-rounded h-weights
__device__ __align__(256) float g_bias[N4];
__device__ __align__(256) float g_Xhi[(size_t)T_SEQ * BATCH * DIN];  // tf32 hi split of tokens
__device__ __align__(256) float g_Xlo[(size_t)T_SEQ * BATCH * DIN];  // tf32 lo split of tokens
__device__ __align__(256) float g_h  [2][BATCH * DOUT];              // ping-pong hidden state (tf32-rounded)
__device__ unsigned g_bar;                                           // grid barrier counter

// ---------------- helpers ----------------
__device__ __forceinline__ float tf32r(float x) {
    uint32_t u;
    asm("cvt.rna.tf32.f32 %0, %1;" : "=r"(u) : "f"(x));
    return __uint_as_float(u);
}

__device__ __forceinline__ void cp16(float* smem_dst, const float* gsrc) {
    unsigned s = (unsigned)__cvta_generic_to_shared(smem_dst);
    asm volatile("cp.async.cg.shared.global [%0], [%1], 16;\n" :: "r"(s), "l"(gsrc));
}

__device__ __forceinline__ void mma8(float* d, const unsigned* a, const unsigned* b) {
    asm volatile(
        "mma.sync.aligned.m16n8k8.row.col.f32.tf32.tf32.f32 "
        "{%0,%1,%2,%3}, {%4,%5,%6,%7}, {%8,%9}, {%0,%1,%2,%3};\n"
        : "+f"(d[0]), "+f"(d[1]), "+f"(d[2]), "+f"(d[3])
        : "r"(a[0]), "r"(a[1]), "r"(a[2]), "r"(a[3]), "r"(b[0]), "r"(b[1]));
}

__device__ __forceinline__ float sigm(float x) { return 1.f / (1.f + __expf(-x)); }

// ---------------- 64x64 (K=1024) tf32 GEMM tile core ----------------
// acc += A[64 x 1024] * B[64 x 1024]^T ; A,B row-major, leading dim 1024 floats.
// 256 threads = 8 warps as 2 (M) x 4 (N); warp tile 32x16; mma m16n8k8.
#define SAS  36               // smem row stride (floats): conflict-free for frag loads, 16B aligned
#define SBUF (64 * SAS)

__device__ __forceinline__ void load_chunk(float* s, const float* g, int tid) {
    // 64 rows x 32 floats, 16B per cp.async, 512 ops / 256 threads
    #pragma unroll
    for (int i = 0; i < 2; i++) {
        int idx = tid + i * 256;
        int r = idx >> 3, c = idx & 7;
        cp16(s + r * SAS + c * 4, g + (size_t)r * 1024 + c * 4);
    }
}

__device__ __forceinline__ void gemm64(const float* __restrict__ Ag,
                                       const float* __restrict__ Bg,
                                       float* sA, float* sB,
                                       float acc[2][2][4], int tid) {
    const int lane = tid & 31, gid = lane >> 2, tig = lane & 3;
    const int wid = tid >> 5, wm = wid >> 2, wn = wid & 3;

    load_chunk(sA, Ag, tid);
    load_chunk(sB, Bg, tid);
    asm volatile("cp.async.commit_group;\n");

    #pragma unroll 1
    for (int c = 0; c < 32; c++) {
        if (c + 1 < 32) {
            load_chunk(sA + ((c + 1) & 1) * SBUF, Ag + (c + 1) * 32, tid);
            load_chunk(sB + ((c + 1) & 1) * SBUF, Bg + (c + 1) * 32, tid);
            asm volatile("cp.async.commit_group;\n");
            asm volatile("cp.async.wait_group 1;\n");
        } else {
            asm volatile("cp.async.wait_group 0;\n");
        }
        __syncthreads();
        const float* a = sA + (c & 1) * SBUF;
        const float* b = sB + (c & 1) * SBUF;
        #pragma unroll
        for (int k8 = 0; k8 < 4; k8++) {
            int k = k8 * 8;
            unsigned af[2][4], bb[2][2];
            #pragma unroll
            for (int mi = 0; mi < 2; mi++) {
                int r0 = wm * 32 + mi * 16 + gid;
                af[mi][0] = __float_as_uint(a[r0 * SAS + k + tig]);
                af[mi][1] = __float_as_uint(a[(r0 + 8) * SAS + k + tig]);
                af[mi][2] = __float_as_uint(a[r0 * SAS + k + tig + 4]);
                af[mi][3] = __float_as_uint(a[(r0 + 8) * SAS + k + tig + 4]);
            }
            #pragma unroll
            for (int ni = 0; ni < 2; ni++) {
                int n0 = wn * 16 + ni * 8 + gid;
                bb[ni][0] = __float_as_uint(b[n0 * SAS + k + tig]);
                bb[ni][1] = __float_as_uint(b[n0 * SAS + k + tig + 4]);
            }
            #pragma unroll
            for (int mi = 0; mi < 2; mi++)
                #pragma unroll
                for (int ni = 0; ni < 2; ni++)
                    mma8(acc[mi][ni], af[mi], bb[ni]);
        }
        __syncthreads();
    }
}

// ---------------- kernel 1: pack weights / split tokens / reset state ----------------
__global__ void __launch_bounds__(256) pack_kernel(
    const float* __restrict__ tokens,
    const float* __restrict__ Wf, const float* __restrict__ bf,
    const float* __restrict__ Wi, const float* __restrict__ bi,
    const float* __restrict__ Wc, const float* __restrict__ bc,
    const float* __restrict__ Wo, const float* __restrict__ bo)
{
    size_t tid = (size_t)blockIdx.x * blockDim.x + threadIdx.x;
    size_t nth = (size_t)gridDim.x * blockDim.x;
    if (tid == 0) g_bar = 0;   // reset grid barrier every launch (graph replays)

    // gate-interleaved weight pack, tf32-rounded: row n = u*4+g
    for (size_t i = tid; i < (size_t)N4 * 1024; i += nth) {
        int n = (int)(i >> 10), k = (int)(i & 1023);
        int u = n >> 2, g = n & 3;
        const float* W = (g == 0) ? Wf : (g == 1) ? Wi : (g == 2) ? Wc : Wo;
        g_Wx[i] = tf32r(W[(size_t)u * 2048 + k]);
        g_Wh[i] = tf32r(W[(size_t)u * 2048 + 1024 + k]);
    }
    for (size_t i = tid; i < (size_t)N4; i += nth) {
        int u = (int)(i >> 2), g = (int)(i & 3);
        const float* bb = (g == 0) ? bf : (g == 1) ? bi : (g == 2) ? bc : bo;
        g_bias[i] = bb[u];
    }
    // tf32 hi/lo split of tokens (2-pass GEMM kills the dominant x rounding error)
    for (size_t i = tid; i < (size_t)T_SEQ * BATCH * DIN; i += nth) {
        float x  = tokens[i];
        float hi = tf32r(x);
        g_Xhi[i] = hi;
        g_Xlo[i] = tf32r(x - hi);
    }
    for (size_t i = tid; i < (size_t)BATCH * DOUT; i += nth)
        g_h[0][i] = 0.f;   // h0 = 0
}

// ---------------- kernel 2: Z = (Xhi+Xlo) @ Wx^T + b for all timesteps ----------------
__global__ void __launch_bounds__(256) precompute_kernel() {
    __shared__ float sA[2 * SBUF], sB[2 * SBUF];
    int tid = threadIdx.x;
    int bx = blockIdx.x;
    int mt = bx >> 6, nt = bx & 63;     // 1024 M-tiles x 64 N-tiles
    size_t m0 = (size_t)mt * 64;
    int n0 = nt * 64;

    float acc[2][2][4] = {};
    gemm64(g_Xhi + m0 * 1024, g_Wx + (size_t)n0 * 1024, sA, sB, acc, tid);
    gemm64(g_Xlo + m0 * 1024, g_Wx + (size_t)n0 * 1024, sA, sB, acc, tid);

    const int lane = tid & 31, gid = lane >> 2, tig = lane & 3;
    const int wid = tid >> 5, wm = wid >> 2, wn = wid & 3;
    #pragma unroll
    for (int mi = 0; mi < 2; mi++)
        #pragma unroll
        for (int ni = 0; ni < 2; ni++) {
            size_t row = m0 + wm * 32 + mi * 16 + gid;
            int col = n0 + wn * 16 + ni * 8 + 2 * tig;
            float b0 = g_bias[col], b1 = g_bias[col + 1];
            float2 v0 = make_float2(acc[mi][ni][0] + b0, acc[mi][ni][1] + b1);
            float2 v1 = make_float2(acc[mi][ni][2] + b0, acc[mi][ni][3] + b1);
            *reinterpret_cast<float2*>(&g_Z[row * N4 + col])       = v0;
            *reinterpret_cast<float2*>(&g_Z[(row + 8) * N4 + col]) = v1;
        }
}

// ---------------- kernel 3: persistent recurrent LSTM ----------------
// 128 CTAs (2 M-tiles x 64 N-tiles), grid barrier per step, c-state in registers.
__global__ void __launch_bounds__(256) lstm_kernel(float* __restrict__ out) {
    __shared__ float sA[2 * SBUF], sB[2 * SBUF];
    int tid = threadIdx.x;
    int bx = blockIdx.x;
    int mt = bx >> 6, nt = bx & 63;
    int m0 = mt * 64, n0 = nt * 64;
    const int lane = tid & 31, gid = lane >> 2, tig = lane & 3;
    const int wid = tid >> 5, wm = wid >> 2, wn = wid & 3;
    const float* Wb = g_Wh + (size_t)n0 * 1024;

    float cst[2][2][2] = {};   // c-state: [mfrag][nfrag][row / row+8] (meaningful on even-tig lanes)

    for (int t = 0; t < T_SEQ; t++) {
        const float* hin  = g_h[t & 1];
        float*       hout = g_h[(t + 1) & 1];
        const float* Zt   = g_Z + (size_t)t * BATCH * N4;

        float acc[2][2][4] = {};
        gemm64(hin + (size_t)m0 * 1024, Wb, sA, sB, acc, tid);

        #pragma unroll
        for (int mi = 0; mi < 2; mi++)
            #pragma unroll
            for (int ni = 0; ni < 2; ni++) {
                int row = m0 + wm * 32 + mi * 16 + gid;
                int col = n0 + wn * 16 + ni * 8 + 2 * tig;
                float2 z0 = *reinterpret_cast<const float2*>(&Zt[(size_t)row * N4 + col]);
                float2 z1 = *reinterpret_cast<const float2*>(&Zt[(size_t)(row + 8) * N4 + col]);
                float v0 = acc[mi][ni][0] + z0.x;   // even lane: gate f   | odd lane: gate g~
                float v1 = acc[mi][ni][1] + z0.y;   // even lane: gate i   | odd lane: gate o
                float v2 = acc[mi][ni][2] + z1.x;
                float v3 = acc[mi][ni][3] + z1.y;
                // swap with lane^1: even lanes collect (g~, o) from odd lanes
                float p0 = __shfl_xor_sync(0xffffffffu, v0, 1);
                float p1 = __shfl_xor_sync(0xffffffffu, v1, 1);
                float p2 = __shfl_xor_sync(0xffffffffu, v2, 1);
                float p3 = __shfl_xor_sync(0xffffffffu, v3, 1);
                if (!(tig & 1)) {
                    int u = col >> 2;
                    {
                        float f = sigm(v0), ii = sigm(v1), gg = tanhf(p0), oo = sigm(p1);
                        float cn = cst[mi][ni][0] * f + ii * gg;
                        cst[mi][ni][0] = cn;
                        float h = oo * tanhf(cn);
                        out[(size_t)t * (BATCH * DOUT) + (size_t)row * DOUT + u] = h;
                        hout[row * DOUT + u] = tf32r(h);
                    }
                    {
                        float f = sigm(v2), ii = sigm(v3), gg = tanhf(p2), oo = sigm(p3);
                        float cn = cst[mi][ni][1] * f + ii * gg;
                        cst[mi][ni][1] = cn;
                        float h = oo * tanhf(cn);
                        out[(size_t)t * (BATCH * DOUT) + (size_t)(row + 8) * DOUT + u] = h;
                        hout[(row + 8) * DOUT + u] = tf32r(h);
                    }
                }
            }

        // grid-wide barrier: all h writes of step t visible before step t+1 reads
        __syncthreads();
        if (tid == 0) {
            __threadfence();
            atomicAdd(&g_bar, 1u);
            unsigned tgt = (unsigned)(t + 1) * GRID_LSTM;
            while (*((volatile unsigned*)&g_bar) < tgt) { }
            __threadfence();
        }
        __syncthreads();
    }
}

// ---------------- launch ----------------
extern "C" void kernel_launch(void* const* d_in, const int* in_sizes, int n_in,
                              void* d_out, int out_size) {
    const float* tokens = (const float*)d_in[0];
    const float* Wf = (const float*)d_in[1]; const float* bf = (const float*)d_in[2];
    const float* Wi = (const float*)d_in[3]; const float* bi = (const float*)d_in[4];
    const float* Wc = (const float*)d_in[5]; const float* bc = (const float*)d_in[6];
    const float* Wo = (const float*)d_in[7]; const float* bo = (const float*)d_in[8];

    pack_kernel<<<2048, 256>>>(tokens, Wf, bf, Wi, bi, Wc, bc, Wo, bo);
    precompute_kernel<<<65536, 256>>>();
    lstm_kernel<<<GRID_LSTM, 256>>>((float*)d_out);
}